// round 12
// baseline (speedup 1.0000x reference)
#include <cuda_runtime.h>
#include <math.h>

// Problem constants (fixed by reference: R=32, G=32768, N=256, SH_DIM=9)
#define G_TOTAL 32768
#define NPTS    256
#define TPB     128
#define GPT     2     // gaussians per thread
#define PPB     32    // points per block -> grid 128x8 = 1024 blocks

// SH normalization constants (degree 2, real basis)
#define C0  0.28209479177387814f
#define C1  0.4886025119029199f
#define C2A 0.5462742152960396f
#define C2B 0.15769578262626002f
#define C2C 0.2730689607973162f
#define NL2E (-1.4426950408889634f)   // -log2(e)

#define NPARAM 21
// SoA scratch: param-major, gaussian pairs packed as float2 (2.75 MB)
__device__ float2 gparams[NPARAM][G_TOTAL / 2];

__device__ __forceinline__ float rsq_approx(float x) {
    float r; asm("rsqrt.approx.f32 %0, %1;" : "=f"(r) : "f"(x)); return r;
}
__device__ __forceinline__ float ex2_approx(float x) {
    float r; asm("ex2.approx.f32 %0, %1;" : "=f"(r) : "f"(x)); return r;
}
__device__ __forceinline__ float rcp_approx(float x) {
    float r; asm("rcp.approx.f32 %0, %1;" : "=f"(r) : "f"(x)); return r;
}

// ---- Kernel A: per-gaussian preprocessing (runs once, 16K threads) ----
__global__ __launch_bounds__(256) void prep_kernel(
    const float* __restrict__ positions,  // [G,3]
    const float* __restrict__ scales,     // [G,3]
    const float4* __restrict__ rotations, // [G] float4
    const float* __restrict__ opacity,    // [G]
    const float* __restrict__ sh,         // [G,9]
    float* __restrict__ out)              // sigma tail written here
{
    const int t  = blockIdx.x * 256 + threadIdx.x;   // 0..16383
    const int g0 = t * 2;

    float prm[2][NPARAM];

    #pragma unroll
    for (int k = 0; k < 2; ++k) {
        const int g = g0 + k;
        const float isx = rcp_approx(scales[3*g + 0] + 1e-6f);
        const float isy = rcp_approx(scales[3*g + 1] + 1e-6f);
        const float isz = rcp_approx(scales[3*g + 2] + 1e-6f);

        const float4 qv = rotations[g];
        const float q0 = qv.x, q1 = qv.y, q2 = qv.z, q3 = qv.w;

        // M = R * diag(1/s)  (quat->matrix without normalization, as reference)
        const float m00 = (1.0f - 2.0f*(q2*q2 + q3*q3)) * isx;
        const float m01 = (2.0f*(q1*q2 - q0*q3))        * isy;
        const float m02 = (2.0f*(q1*q3 + q0*q2))        * isz;
        const float m10 = (2.0f*(q1*q2 + q0*q3))        * isx;
        const float m11 = (1.0f - 2.0f*(q1*q1 + q3*q3)) * isy;
        const float m12 = (2.0f*(q2*q3 - q0*q1))        * isz;
        const float m20 = (2.0f*(q1*q3 - q0*q2))        * isx;
        const float m21 = (2.0f*(q2*q3 + q0*q1))        * isy;
        const float m22 = (1.0f - 2.0f*(q1*q1 + q2*q2)) * isz;

        const float px = positions[3*g + 0];
        const float py = positions[3*g + 1];
        const float pz = positions[3*g + 2];

        prm[k][0] = m00;  prm[k][1] = m01;  prm[k][2] = m02;
        prm[k][3] = m10;  prm[k][4] = m11;  prm[k][5] = m12;
        prm[k][6] = m20;  prm[k][7] = m21;  prm[k][8] = m22;
        prm[k][9]  = -(m00*px + m01*py + m02*pz);
        prm[k][10] = -(m10*px + m11*py + m12*pz);
        prm[k][11] = -(m20*px + m21*py + m22*pz);

        // Fold SH norm constants AND -log2(e) (ex2 sigmoid) into coefficients
        prm[k][12] = sh[9*g + 1] * (C1 * NL2E);
        prm[k][13] = sh[9*g + 2] * (C1 * NL2E);
        prm[k][14] = sh[9*g + 3] * (C1 * NL2E);
        prm[k][15] = sh[9*g + 4] * (C2A * NL2E);
        prm[k][16] = sh[9*g + 5] * (C2A * NL2E);
        prm[k][17] = sh[9*g + 6] * (3.0f * C2B * NL2E);
        prm[k][18] = sh[9*g + 7] * (C2A * NL2E);
        prm[k][19] = sh[9*g + 8] * (C2C * NL2E);
        prm[k][20] = (sh[9*g + 0] * C0 - sh[9*g + 6] * C2B) * NL2E;
    }

    #pragma unroll
    for (int j = 0; j < NPARAM; ++j)
        gparams[j][t] = make_float2(prm[0][j], prm[1][j]);

    // sigma = softplus(opacity)
    float2 sg;
    const float o0 = opacity[g0];
    const float o1 = opacity[g0 + 1];
    sg.x = fmaxf(o0, 0.0f) + log1pf(__expf(-fabsf(o0)));
    sg.y = fmaxf(o1, 0.0f) + log1pf(__expf(-fabsf(o1)));
    *(float2*)(out + (size_t)NPTS * G_TOTAL + g0) = sg;
}

// ---- Kernel B: mainloop ----
__global__ __launch_bounds__(TPB) void gausssplat_kernel(
    const float* __restrict__ points,     // [N,3]
    float* __restrict__ out)              // [N*G rgb]
{
    const int tg    = blockIdx.x * TPB + threadIdx.x;   // gaussian-pair index
    const int g0    = tg * GPT;
    const int nbase = blockIdx.y * PPB;

    // Stage point chunk as float4 (pre-scaled by 1/4)
    __shared__ float4 sp[PPB];
    if (threadIdx.x < PPB) {
        const int n = nbase + threadIdx.x;
        sp[threadIdx.x] = make_float4(points[3*n + 0] * 0.25f,
                                      points[3*n + 1] * 0.25f,
                                      points[3*n + 2] * 0.25f, 0.0f);
    }
    __syncthreads();

    // 21 coalesced LDG.64 loads: all per-gaussian params
    const float2 M00 = gparams[0][tg],  M01 = gparams[1][tg],  M02 = gparams[2][tg];
    const float2 M10 = gparams[3][tg],  M11 = gparams[4][tg],  M12 = gparams[5][tg];
    const float2 M20 = gparams[6][tg],  M21 = gparams[7][tg],  M22 = gparams[8][tg];
    const float2 NCX = gparams[9][tg],  NCY = gparams[10][tg], NCZ = gparams[11][tg];
    const float2 S1  = gparams[12][tg], S2  = gparams[13][tg], S3  = gparams[14][tg];
    const float2 S4  = gparams[15][tg], S5  = gparams[16][tg], S63 = gparams[17][tg];
    const float2 S7  = gparams[18][tg], S8  = gparams[19][tg], BSE = gparams[20][tg];

    const float m00[2] = {M00.x, M00.y}, m01[2] = {M01.x, M01.y}, m02[2] = {M02.x, M02.y};
    const float m10[2] = {M10.x, M10.y}, m11[2] = {M11.x, M11.y}, m12[2] = {M12.x, M12.y};
    const float m20[2] = {M20.x, M20.y}, m21[2] = {M21.x, M21.y}, m22[2] = {M22.x, M22.y};
    const float ncx[2] = {NCX.x, NCX.y}, ncy[2] = {NCY.x, NCY.y}, ncz[2] = {NCZ.x, NCZ.y};
    const float s1c[2] = {S1.x, S1.y},   s2c[2] = {S2.x, S2.y},   s3c[2] = {S3.x, S3.y};
    const float s4c[2] = {S4.x, S4.y},   s5c[2] = {S5.x, S5.y},   s63[2] = {S63.x, S63.y};
    const float s7c[2] = {S7.x, S7.y},   s8c[2] = {S8.x, S8.y},   bse[2] = {BSE.x, BSE.y};

    float* __restrict__ orow = out + (size_t)nbase * G_TOTAL + g0;

    #pragma unroll
    for (int i = 0; i < PPB; ++i) {
        const float4 p = sp[i];
        float res[GPT];

        #pragma unroll
        for (int k = 0; k < GPT; ++k) {
            // rotated+scaled diff: M*p - c (9 FMA)
            const float rx = fmaf(m00[k], p.x, fmaf(m01[k], p.y, fmaf(m02[k], p.z, ncx[k])));
            const float ry = fmaf(m10[k], p.x, fmaf(m11[k], p.y, fmaf(m12[k], p.z, ncy[k])));
            const float rz = fmaf(m20[k], p.x, fmaf(m21[k], p.y, fmaf(m22[k], p.z, ncz[k])));

            const float zz = rz * rz;
            const float n2 = fmaf(rx, rx, fmaf(ry, ry, zz));
            const float inv = rsq_approx(n2);

            // degree-1 (unnormalized)
            const float lin = fmaf(s1c[k], ry, fmaf(s2c[k], rz, s3c[k] * rx));
            // degree-2 (unnormalized, Horner)
            const float t1 = fmaf(s8c[k], rx, fmaf(s4c[k], ry, s7c[k] * rz));
            const float t2 = fmaf(-s8c[k], ry, s5c[k] * rz);
            const float q  = fmaf(rx, t1, fmaf(ry, t2, s63[k] * zz));

            // v' = -log2e*v, nested: (q*inv + lin)*inv + bse
            const float v = fmaf(fmaf(q, inv, lin), inv, bse[k]);
            res[k] = rcp_approx(1.0f + ex2_approx(v));
        }

        *(float2*)&orow[(size_t)i * G_TOTAL] = make_float2(res[0], res[1]);
    }
}

extern "C" void kernel_launch(void* const* d_in, const int* in_sizes, int n_in,
                              void* d_out, int out_size) {
    const float* points    = (const float*)d_in[0];
    const float* positions = (const float*)d_in[1];
    const float* scales    = (const float*)d_in[2];
    const float4* rotations= (const float4*)d_in[3];
    const float* opacity   = (const float*)d_in[4];
    const float* sh        = (const float*)d_in[5];
    float* out = (float*)d_out;

    prep_kernel<<<G_TOTAL / (2 * 256), 256>>>(positions, scales, rotations,
                                              opacity, sh, out);
    dim3 grid(G_TOTAL / (TPB * GPT), NPTS / PPB);
    gausssplat_kernel<<<grid, TPB>>>(points, out);
}

// round 13
// speedup vs baseline: 1.1050x; 1.1050x over previous
#include <cuda_runtime.h>
#include <math.h>

// Problem constants (fixed by reference: R=32, G=32768, N=256, SH_DIM=9)
#define G_TOTAL 32768
#define NPTS    256
#define TPB     128
#define GPT     2     // gaussians per thread
#define PPB     32    // points per block -> grid 128x8 = 1024 blocks
#define GPB     (TPB * GPT)   // gaussians per block = 256

// SH normalization constants (degree 2, real basis)
#define C0  0.28209479177387814f
#define C1  0.4886025119029199f
#define C2A 0.5462742152960396f
#define C2B 0.15769578262626002f
#define C2C 0.2730689607973162f
#define NL2E (-1.4426950408889634f)   // -log2(e)

// smem float offsets for staged raw params (per block: 5120 floats = 20 KB)
#define OFF_POS 0        // 3*GPB = 768
#define OFF_SCL 768      // 3*GPB = 768
#define OFF_ROT 1536     // 4*GPB = 1024
#define OFF_SH  2560     // 9*GPB = 2304
#define OFF_OPA 4864     // GPB   = 256
#define RAW_TOT 5120

__device__ __forceinline__ float rsq_approx(float x) {
    float r; asm("rsqrt.approx.f32 %0, %1;" : "=f"(r) : "f"(x)); return r;
}
__device__ __forceinline__ float ex2_approx(float x) {
    float r; asm("ex2.approx.f32 %0, %1;" : "=f"(r) : "f"(x)); return r;
}
__device__ __forceinline__ float rcp_approx(float x) {
    float r; asm("rcp.approx.f32 %0, %1;" : "=f"(r) : "f"(x)); return r;
}

__global__ __launch_bounds__(TPB) void gausssplat_kernel(
    const float* __restrict__ points,     // [N,3]
    const float* __restrict__ positions,  // [G,3]
    const float* __restrict__ scales,     // [G,3]
    const float4* __restrict__ rotations, // [G] float4 (16B aligned)
    const float* __restrict__ opacity,    // [G]
    const float* __restrict__ sh,         // [G,9]
    float* __restrict__ out)              // [N*G rgb][G sigma]
{
    const int tid   = threadIdx.x;
    const int gb    = blockIdx.x * GPB;       // block's first gaussian
    const int nbase = blockIdx.y * PPB;

    __shared__ float praw[RAW_TOT];
    __shared__ float4 sp[PPB];

    // ---- Coalesced staging of all per-gaussian raw inputs (float4) ----
    {
        float4* pr4 = (float4*)praw;
        const float4* p4 = (const float4*)(positions + 3 * gb);
        const float4* s4 = (const float4*)(scales    + 3 * gb);
        const float4* r4 = (const float4*)(rotations + gb);
        const float4* h4 = (const float4*)(sh        + 9 * gb);
        const float4* o4 = (const float4*)(opacity   + gb);
        #pragma unroll
        for (int i = tid; i < 192; i += TPB) pr4[i]                 = p4[i];
        #pragma unroll
        for (int i = tid; i < 192; i += TPB) pr4[192 + i]           = s4[i];
        #pragma unroll
        for (int i = tid; i < 256; i += TPB) pr4[384 + i]           = r4[i];
        #pragma unroll
        for (int i = tid; i < 576; i += TPB) pr4[640 + i]           = h4[i];
        if (tid < 64) pr4[1216 + tid] = o4[tid];

        if (tid < PPB) {
            const int n = nbase + tid;
            sp[tid] = make_float4(points[3*n + 0] * 0.25f,
                                  points[3*n + 1] * 0.25f,
                                  points[3*n + 2] * 0.25f, 0.0f);
        }
    }
    __syncthreads();

    // ---- Per-gaussian precompute from shared (LDS, near-conflict-free) ----
    float m00[GPT], m01[GPT], m02[GPT];
    float m10[GPT], m11[GPT], m12[GPT];
    float m20[GPT], m21[GPT], m22[GPT];
    float ncx[GPT], ncy[GPT], ncz[GPT];
    float s1c[GPT], s2c[GPT], s3c[GPT];
    float s4c[GPT], s5c[GPT], s7c[GPT];
    float s8c[GPT], s63[GPT], bse[GPT];

    #pragma unroll
    for (int k = 0; k < GPT; ++k) {
        const int lg = tid * GPT + k;          // local gaussian 0..255
        const float isx = rcp_approx(praw[OFF_SCL + 3*lg + 0] + 1e-6f);
        const float isy = rcp_approx(praw[OFF_SCL + 3*lg + 1] + 1e-6f);
        const float isz = rcp_approx(praw[OFF_SCL + 3*lg + 2] + 1e-6f);

        const float4 qv = ((const float4*)(praw + OFF_ROT))[lg];
        const float q0 = qv.x, q1 = qv.y, q2 = qv.z, q3 = qv.w;

        // M = R * diag(1/s)  (quat->matrix without normalization, as reference)
        m00[k] = (1.0f - 2.0f*(q2*q2 + q3*q3)) * isx;
        m01[k] = (2.0f*(q1*q2 - q0*q3))        * isy;
        m02[k] = (2.0f*(q1*q3 + q0*q2))        * isz;
        m10[k] = (2.0f*(q1*q2 + q0*q3))        * isx;
        m11[k] = (1.0f - 2.0f*(q1*q1 + q3*q3)) * isy;
        m12[k] = (2.0f*(q2*q3 - q0*q1))        * isz;
        m20[k] = (2.0f*(q1*q3 - q0*q2))        * isx;
        m21[k] = (2.0f*(q2*q3 + q0*q1))        * isy;
        m22[k] = (1.0f - 2.0f*(q1*q1 + q2*q2)) * isz;

        const float px = praw[OFF_POS + 3*lg + 0];
        const float py = praw[OFF_POS + 3*lg + 1];
        const float pz = praw[OFF_POS + 3*lg + 2];
        ncx[k] = -(m00[k]*px + m01[k]*py + m02[k]*pz);
        ncy[k] = -(m10[k]*px + m11[k]*py + m12[k]*pz);
        ncz[k] = -(m20[k]*px + m21[k]*py + m22[k]*pz);

        // Fold SH norm constants AND -log2(e) (ex2 sigmoid) into coefficients
        const float* shr = praw + OFF_SH + 9*lg;
        s1c[k] = shr[1] * (C1 * NL2E);
        s2c[k] = shr[2] * (C1 * NL2E);
        s3c[k] = shr[3] * (C1 * NL2E);
        s4c[k] = shr[4] * (C2A * NL2E);
        s5c[k] = shr[5] * (C2A * NL2E);
        s63[k] = shr[6] * (3.0f * C2B * NL2E);
        s7c[k] = shr[7] * (C2A * NL2E);
        s8c[k] = shr[8] * (C2C * NL2E);
        bse[k] = (shr[0] * C0 - shr[6] * C2B) * NL2E;
    }

    // sigma = softplus(opacity) once
    if (blockIdx.y == 0) {
        float2 sg;
        const float o0 = praw[OFF_OPA + tid * GPT + 0];
        const float o1 = praw[OFF_OPA + tid * GPT + 1];
        sg.x = fmaxf(o0, 0.0f) + log1pf(__expf(-fabsf(o0)));
        sg.y = fmaxf(o1, 0.0f) + log1pf(__expf(-fabsf(o1)));
        *(float2*)(out + (size_t)NPTS * G_TOTAL + gb + tid * GPT) = sg;
    }

    float* __restrict__ orow = out + (size_t)nbase * G_TOTAL + gb + tid * GPT;

    #pragma unroll
    for (int i = 0; i < PPB; ++i) {
        const float4 p = sp[i];
        float res[GPT];

        #pragma unroll
        for (int k = 0; k < GPT; ++k) {
            // rotated+scaled diff: M*p - c (9 FMA)
            const float rx = fmaf(m00[k], p.x, fmaf(m01[k], p.y, fmaf(m02[k], p.z, ncx[k])));
            const float ry = fmaf(m10[k], p.x, fmaf(m11[k], p.y, fmaf(m12[k], p.z, ncy[k])));
            const float rz = fmaf(m20[k], p.x, fmaf(m21[k], p.y, fmaf(m22[k], p.z, ncz[k])));

            const float zz = rz * rz;
            const float n2 = fmaf(rx, rx, fmaf(ry, ry, zz));
            const float inv = rsq_approx(n2);

            // degree-1 (unnormalized)
            const float lin = fmaf(s1c[k], ry, fmaf(s2c[k], rz, s3c[k] * rx));
            // degree-2 (unnormalized, Horner)
            const float t1 = fmaf(s8c[k], rx, fmaf(s4c[k], ry, s7c[k] * rz));
            const float t2 = fmaf(-s8c[k], ry, s5c[k] * rz);
            const float q  = fmaf(rx, t1, fmaf(ry, t2, s63[k] * zz));

            // v' = -log2e*v, nested: (q*inv + lin)*inv + bse
            const float v = fmaf(fmaf(q, inv, lin), inv, bse[k]);
            res[k] = rcp_approx(1.0f + ex2_approx(v));
        }

        *(float2*)&orow[(size_t)i * G_TOTAL] = make_float2(res[0], res[1]);
    }
}

extern "C" void kernel_launch(void* const* d_in, const int* in_sizes, int n_in,
                              void* d_out, int out_size) {
    const float* points    = (const float*)d_in[0];
    const float* positions = (const float*)d_in[1];
    const float* scales    = (const float*)d_in[2];
    const float4* rotations= (const float4*)d_in[3];
    const float* opacity   = (const float*)d_in[4];
    const float* sh        = (const float*)d_in[5];
    float* out = (float*)d_out;

    dim3 grid(G_TOTAL / GPB, NPTS / PPB);
    gausssplat_kernel<<<grid, TPB>>>(points, positions, scales, rotations,
                                     opacity, sh, out);
}

// round 14
// speedup vs baseline: 1.2581x; 1.1385x over previous
#include <cuda_runtime.h>
#include <math.h>

// Problem constants (fixed by reference: R=32, G=32768, N=256, SH_DIM=9)
#define G_TOTAL 32768
#define NPTS    256
#define TPB     128
#define PPB     32    // points per block -> grid 256x8 = 2048 blocks

// SH normalization constants (degree 2, real basis)
#define C0  0.28209479177387814f
#define C1  0.4886025119029199f
#define C2A 0.5462742152960396f
#define C2B 0.15769578262626002f
#define C2C 0.2730689607973162f
#define NL2E (-1.4426950408889634f)   // -log2(e)

__device__ __forceinline__ float rsq_approx(float x) {
    float r; asm("rsqrt.approx.f32 %0, %1;" : "=f"(r) : "f"(x)); return r;
}
__device__ __forceinline__ float ex2_approx(float x) {
    float r; asm("ex2.approx.f32 %0, %1;" : "=f"(r) : "f"(x)); return r;
}
__device__ __forceinline__ float rcp_approx(float x) {
    float r; asm("rcp.approx.f32 %0, %1;" : "=f"(r) : "f"(x)); return r;
}

__global__ __launch_bounds__(TPB) void gausssplat_kernel(
    const float* __restrict__ points,     // [N,3]
    const float* __restrict__ positions,  // [G,3]
    const float* __restrict__ scales,     // [G,3]
    const float4* __restrict__ rotations, // [G] float4 (16B aligned)
    const float* __restrict__ opacity,    // [G]
    const float* __restrict__ sh,         // [G,9]
    float* __restrict__ out)              // [N*G rgb][G sigma]
{
    const int g     = blockIdx.x * TPB + threadIdx.x;   // one gaussian per thread
    const int nbase = blockIdx.y * PPB;

    // Stage point chunk as float4 (pre-scaled by 1/4): one LDS.128 per iter
    __shared__ float4 sp[PPB];
    if (threadIdx.x < PPB) {
        const int n = nbase + threadIdx.x;
        sp[threadIdx.x] = make_float4(points[3*n + 0] * 0.25f,
                                      points[3*n + 1] * 0.25f,
                                      points[3*n + 2] * 0.25f, 0.0f);
    }
    __syncthreads();

    // ---- Per-gaussian precompute (amortized over PPB points) ----
    const float isx = rcp_approx(scales[3*g + 0] + 1e-6f);
    const float isy = rcp_approx(scales[3*g + 1] + 1e-6f);
    const float isz = rcp_approx(scales[3*g + 2] + 1e-6f);

    const float4 qv = rotations[g];    // one LDG.128
    const float q0 = qv.x, q1 = qv.y, q2 = qv.z, q3 = qv.w;

    // M = R * diag(1/s)  (quat->matrix without normalization, as reference)
    const float m00 = (1.0f - 2.0f*(q2*q2 + q3*q3)) * isx;
    const float m01 = (2.0f*(q1*q2 - q0*q3))        * isy;
    const float m02 = (2.0f*(q1*q3 + q0*q2))        * isz;
    const float m10 = (2.0f*(q1*q2 + q0*q3))        * isx;
    const float m11 = (1.0f - 2.0f*(q1*q1 + q3*q3)) * isy;
    const float m12 = (2.0f*(q2*q3 - q0*q1))        * isz;
    const float m20 = (2.0f*(q1*q3 - q0*q2))        * isx;
    const float m21 = (2.0f*(q2*q3 + q0*q1))        * isy;
    const float m22 = (1.0f - 2.0f*(q1*q1 + q2*q2)) * isz;

    const float px = positions[3*g + 0];
    const float py = positions[3*g + 1];
    const float pz = positions[3*g + 2];
    const float ncx = -(m00*px + m01*py + m02*pz);
    const float ncy = -(m10*px + m11*py + m12*pz);
    const float ncz = -(m20*px + m21*py + m22*pz);

    // Fold SH norm constants AND -log2(e) (ex2 sigmoid) into coefficients
    const float s1c = sh[9*g + 1] * (C1 * NL2E);
    const float s2c = sh[9*g + 2] * (C1 * NL2E);
    const float s3c = sh[9*g + 3] * (C1 * NL2E);
    const float s4c = sh[9*g + 4] * (C2A * NL2E);
    const float s5c = sh[9*g + 5] * (C2A * NL2E);
    const float s63 = sh[9*g + 6] * (3.0f * C2B * NL2E);
    const float s7c = sh[9*g + 7] * (C2A * NL2E);
    const float s8c = sh[9*g + 8] * (C2C * NL2E);
    const float bse = (sh[9*g + 0] * C0 - sh[9*g + 6] * C2B) * NL2E;

    // sigma = softplus(opacity) once
    if (blockIdx.y == 0) {
        const float o = opacity[g];
        out[(size_t)NPTS * G_TOTAL + g] =
            fmaxf(o, 0.0f) + log1pf(__expf(-fabsf(o)));
    }

    float* __restrict__ orow = out + (size_t)nbase * G_TOTAL + g;

    #pragma unroll
    for (int i = 0; i < PPB; ++i) {
        const float4 p = sp[i];

        // rotated+scaled diff: M*p - c (9 FMA)
        const float rx = fmaf(m00, p.x, fmaf(m01, p.y, fmaf(m02, p.z, ncx)));
        const float ry = fmaf(m10, p.x, fmaf(m11, p.y, fmaf(m12, p.z, ncy)));
        const float rz = fmaf(m20, p.x, fmaf(m21, p.y, fmaf(m22, p.z, ncz)));

        const float zz = rz * rz;
        const float n2 = fmaf(rx, rx, fmaf(ry, ry, zz));
        const float inv = rsq_approx(n2);

        // degree-1 (unnormalized)
        const float lin = fmaf(s1c, ry, fmaf(s2c, rz, s3c * rx));
        // degree-2 (unnormalized, Horner): x(s8x+s4y+s7z) + y(s5z-s8y) + s63 z^2
        const float t1 = fmaf(s8c, rx, fmaf(s4c, ry, s7c * rz));
        const float t2 = fmaf(-s8c, ry, s5c * rz);
        const float q  = fmaf(rx, t1, fmaf(ry, t2, s63 * zz));

        // v' = -log2e*v, nested: (q*inv + lin)*inv + bse
        const float v = fmaf(fmaf(q, inv, lin), inv, bse);
        orow[(size_t)i * G_TOTAL] = rcp_approx(1.0f + ex2_approx(v));
    }
}

extern "C" void kernel_launch(void* const* d_in, const int* in_sizes, int n_in,
                              void* d_out, int out_size) {
    const float* points    = (const float*)d_in[0];
    const float* positions = (const float*)d_in[1];
    const float* scales    = (const float*)d_in[2];
    const float4* rotations= (const float4*)d_in[3];
    const float* opacity   = (const float*)d_in[4];
    const float* sh        = (const float*)d_in[5];
    float* out = (float*)d_out;

    dim3 grid(G_TOTAL / TPB, NPTS / PPB);
    gausssplat_kernel<<<grid, TPB>>>(points, positions, scales, rotations,
                                     opacity, sh, out);
}